// round 11
// baseline (speedup 1.0000x reference)
#include <cuda_runtime.h>

typedef unsigned long long u64;

#define FEAT 768
#define KT   32      // k-tile
#define RPW  16      // rows per warp
#define RPB  128     // rows per block (8 warps)

// ---------------- scratch (device globals; no allocation) ----------------
__device__ float g_agg[6ull * 65536 * 32];   // 6 aggregation buffers [B,32]
__device__ float g_emb[3ull * 65536 * 32];   // h / pos / neg entity embeddings
__device__ float g_R[1344 * 32];             // normalized relation embeddings
__device__ float g_Cin[1024];                // W_ent[:,768:800] @ W_in
__device__ float g_Cout[1024];               // W_ent[:,800:832] @ W_out
__device__ float g_bias[32];                 // folded bias

// ---------------- f32x2 packed-math helpers ----------------
__device__ __forceinline__ u64 ffma2(u64 a, u64 b, u64 c) {
    u64 d;
    asm("fma.rn.f32x2 %0, %1, %2, %3;" : "=l"(d) : "l"(a), "l"(b), "l"(c));
    return d;
}
__device__ __forceinline__ u64 pk(float lo, float hi) {
    u64 r; asm("mov.b64 %0, {%1, %2};" : "=l"(r) : "f"(lo), "f"(hi)); return r;
}
__device__ __forceinline__ float2 upk(u64 v) {
    float2 r; asm("mov.b64 {%0, %1}, %2;" : "=f"(r.x), "=f"(r.y) : "l"(v)); return r;
}

// ---------------- zero the aggregation scratch ----------------
__global__ void zero_kernel(long n4) {
    float4* p = reinterpret_cast<float4*>(g_agg);
    long i = blockIdx.x * (long)blockDim.x + threadIdx.x;
    long stride = (long)gridDim.x * blockDim.x;
    float4 z = make_float4(0.f, 0.f, 0.f, 0.f);
    for (; i < n4; i += stride) p[i] = z;
}

// ---------------- fold W_in/W_out into W_ent tail: C_in/C_out + bias ----------------
// 4 blocks x 256 threads: gid -> (j = output row 0..31, d = col 0..31).
// 256-thread blocks keep reg pressure irrelevant (fix for "too many resources").
__global__ __launch_bounds__(256) void setup_kernel(
        const float* __restrict__ W_in,  const float* __restrict__ b_in,
        const float* __restrict__ W_out, const float* __restrict__ b_out,
        const float* __restrict__ W_ent, const float* __restrict__ b_ent) {
    int gid = blockIdx.x * 256 + threadIdx.x;   // 0..1023
    int j = gid >> 5, d = gid & 31;
    float ci = 0.f, co = 0.f;
    #pragma unroll
    for (int c = 0; c < 32; ++c) {
        ci += W_ent[j * 832 + 768 + c] * W_in[c * 32 + d];
        co += W_ent[j * 832 + 800 + c] * W_out[c * 32 + d];
    }
    g_Cin[j * 32 + d] = ci;
    g_Cout[j * 32 + d] = co;
    if (d == 0) {
        float b = b_ent[j];
        #pragma unroll
        for (int c = 0; c < 32; ++c)
            b += b_in[c] * W_ent[j * 832 + 768 + c] + b_out[c] * W_ent[j * 832 + 800 + c];
        g_bias[j] = b;
    }
}

// ---------------- precompute normalized relation embeddings (1315 rows) ----------------
__global__ void relprep_kernel(const float* __restrict__ rel_emb, const float* __restrict__ W_rel,
                               const float* __restrict__ b_rel, int nrels) {
    int w = (blockIdx.x * blockDim.x + threadIdx.x) >> 5;
    int j = threadIdx.x & 31;
    if (w >= nrels) return;
    float rv = rel_emb[w * 32 + j];
    float acc = b_rel[j];
    const float* wr = W_rel + j * 32;
    #pragma unroll
    for (int d = 0; d < 32; ++d)
        acc = fmaf(__shfl_sync(0xffffffffu, rv, d), __ldg(wr + d), acc);
    float s = acc * acc;
    #pragma unroll
    for (int o = 16; o; o >>= 1) s += __shfl_xor_sync(0xffffffffu, s, o);
    g_R[w * 32 + j] = acc / fmaxf(sqrtf(s), 1e-12f);
}

// ---------------- fused scatter-add over all 6 incidence matrices ----------------
// agg[buf][row] += val * rel_emb[col]; one launch, block -> (matrix, chunk)
__global__ void scatter6_kernel(const int* __restrict__ r0, const int* __restrict__ c0, const float* __restrict__ v0,
                                const int* __restrict__ r1, const int* __restrict__ c1, const float* __restrict__ v1,
                                const int* __restrict__ r2, const int* __restrict__ c2, const float* __restrict__ v2,
                                const int* __restrict__ r3, const int* __restrict__ c3, const float* __restrict__ v3,
                                const int* __restrict__ r4, const int* __restrict__ c4, const float* __restrict__ v4,
                                const int* __restrict__ r5, const int* __restrict__ c5, const float* __restrict__ v5,
                                int n0, int n1, int n2, int n3, int n4_, int n5,
                                const float* __restrict__ rel_emb, int nB, int nbpm) {
    const int m = blockIdx.x / nbpm;
    const int i = (blockIdx.x - m * nbpm) * blockDim.x + threadIdx.x;
    const int* rows; const int* cols; const float* vals; int nnz;
    switch (m) {
        case 0: rows = r0; cols = c0; vals = v0; nnz = n0;  break;
        case 1: rows = r1; cols = c1; vals = v1; nnz = n1;  break;
        case 2: rows = r2; cols = c2; vals = v2; nnz = n2;  break;
        case 3: rows = r3; cols = c3; vals = v3; nnz = n3;  break;
        case 4: rows = r4; cols = c4; vals = v4; nnz = n4_; break;
        default:rows = r5; cols = c5; vals = v5; nnz = n5;  break;
    }
    if (i >= nnz) return;
    int r = rows[i];
    int c = cols[i];
    float v = vals[i];
    const float4* re = reinterpret_cast<const float4*>(rel_emb + (long)c * 32);
    float* base = g_agg + (long)m * nB * 32 + (long)r * 32;
    float4 s[8];
    #pragma unroll
    for (int q = 0; q < 8; ++q) {
        float4 w = __ldg(re + q);
        s[q] = make_float4(v * w.x, v * w.y, v * w.z, v * w.w);
    }
    #pragma unroll
    for (int q = 0; q < 8; ++q) {
        asm volatile("red.global.add.v4.f32 [%0], {%1, %2, %3, %4};"
                     :: "l"(base + q * 4), "f"(s[q].x), "f"(s[q].y), "f"(s[q].z), "f"(s[q].w)
                     : "memory");
    }
}

// ---------------- entity embedding for ALL 3 sides in one launch ----------------
// e = normalize([feat|agg_in|agg_out] @ M^T + bias); side = blockIdx.x / (nB/RPB)
__global__ __launch_bounds__(256, 2) void ent_emb_kernel(const float* __restrict__ feat_h,
                                                         const float* __restrict__ feat_p,
                                                         const float* __restrict__ feat_n,
                                                         const float* __restrict__ W_ent,
                                                         int nB) {
    __shared__ __align__(16) float As[RPB][KT];   // 16 KB A tile
    __shared__ u64 Ws[KT / 2][32];                // 4 KB W tile, k-paired

    const int tid = threadIdx.x;
    const int warp = tid >> 5, lane = tid & 31;
    const int bpg = nB / RPB;                     // blocks per side
    const int side = blockIdx.x / bpg;
    const int row0 = (blockIdx.x - side * bpg) * RPB;

    const float* feat = (side == 0) ? feat_h : (side == 1) ? feat_p : feat_n;
    const float* aggin  = g_agg + (long)(2 * side)     * nB * 32;
    const float* aggout = g_agg + (long)(2 * side + 1) * nB * 32;
    float*       emb    = g_emb + (long)side * nB * 32;

    u64 acc[RPW];
    #pragma unroll
    for (int i = 0; i < RPW; ++i) acc[i] = 0ull;

    const int sr = tid >> 3;           // staging row (0..31)
    const int sc = (tid & 7) * 4;      // staging col (0,4,..,28)

    for (int t = 0; t < 26; ++t) {
        __syncthreads();
        // ---- stage A tile [128 rows x 32 k], coalesced float4 ----
        const float* asrc; long astr;
        if (t < 24)       { asrc = feat   + (long)row0 * FEAT + t * KT; astr = FEAT; }
        else if (t == 24) { asrc = aggin  + (long)row0 * 32;            astr = 32;   }
        else              { asrc = aggout + (long)row0 * 32;            astr = 32;   }
        #pragma unroll
        for (int rr = 0; rr < 4; ++rr) {
            float4 v = *reinterpret_cast<const float4*>(asrc + (long)(sr + rr * 32) * astr + sc);
            *reinterpret_cast<float4*>(&As[sr + rr * 32][sc]) = v;
        }
        // ---- stage W tile, pre-paired over k ----
        {
            const float* wsrc;
            if (t < 24)       wsrc = W_ent + (long)sr * 832 + t * KT + sc;
            else if (t == 24) wsrc = g_Cin  + sr * 32 + sc;
            else              wsrc = g_Cout + sr * 32 + sc;
            float4 wv = *reinterpret_cast<const float4*>(wsrc);
            Ws[(sc >> 1)][sr]     = pk(wv.x, wv.y);
            Ws[(sc >> 1) + 1][sr] = pk(wv.z, wv.w);
        }
        __syncthreads();
        // ---- W into registers (lane = output col), reused over RPW rows ----
        u64 wreg[KT / 2];
        #pragma unroll
        for (int p = 0; p < KT / 2; ++p) wreg[p] = Ws[p][lane];
        // ---- packed FMA mainloop: chunk-outer / row-inner for ILP ----
        #pragma unroll
        for (int c = 0; c < KT / 4; ++c) {
            #pragma unroll
            for (int rr = 0; rr < RPW; ++rr) {
                const int r = warp * RPW + rr;
                ulonglong2 a = *reinterpret_cast<const ulonglong2*>(&As[r][c * 4]);
                acc[rr] = ffma2(a.x, wreg[2 * c],     acc[rr]);
                acc[rr] = ffma2(a.y, wreg[2 * c + 1], acc[rr]);
            }
        }
    }
    // ---- epilogue: bias, row-norm, write ----
    float bj = g_bias[lane];
    #pragma unroll
    for (int rr = 0; rr < RPW; ++rr) {
        float2 p = upk(acc[rr]);
        float e = p.x + p.y + bj;
        float s = e * e;
        #pragma unroll
        for (int o = 16; o; o >>= 1) s += __shfl_xor_sync(0xffffffffu, s, o);
        float inv = 1.f / fmaxf(sqrtf(s), 1e-12f);
        emb[(long)(row0 + warp * RPW + rr) * 32 + lane] = e * inv;
    }
}

// ---------------- scores: 8 lanes per entity, float4 per lane ----------------
__global__ void score_kernel(const int* __restrict__ eid, float* __restrict__ out, int nB) {
    int gt = blockIdx.x * blockDim.x + threadIdx.x;
    int ent = gt >> 3;
    if (ent >= nB) return;
    int sub = gt & 7;
    int e = eid[ent];
    const float4* R4 = reinterpret_cast<const float4*>(g_R);
    const float4* h4 = reinterpret_cast<const float4*>(g_emb);
    const float4* p4 = h4 + (long)nB * 8;
    const float4* n4 = h4 + (long)2 * nB * 8;
    float4 r = R4[e * 8 + sub];
    float4 h = h4[(long)ent * 8 + sub];
    float4 p = p4[(long)ent * 8 + sub];
    float4 n = n4[(long)ent * 8 + sub];
    float hx = h.x + r.x, hy = h.y + r.y, hz = h.z + r.z, hw = h.w + r.w;
    float dx, dy, dz, dw;
    dx = hx - p.x; dy = hy - p.y; dz = hz - p.z; dw = hw - p.w;
    float sp = dx * dx + dy * dy + dz * dz + dw * dw;
    dx = hx - n.x; dy = hy - n.y; dz = hz - n.z; dw = hw - n.w;
    float sn = dx * dx + dy * dy + dz * dz + dw * dw;
    #pragma unroll
    for (int o = 4; o; o >>= 1) {
        sp += __shfl_xor_sync(0xffffffffu, sp, o);
        sn += __shfl_xor_sync(0xffffffffu, sn, o);
    }
    if (sub == 0) {
        out[ent]      = sqrtf(sp);
        out[nB + ent] = sqrtf(sn);
    }
}

// ---------------- launch ----------------
extern "C" void kernel_launch(void* const* d_in, const int* in_sizes, int n_in,
                              void* d_out, int out_size) {
    const int*   eid     = (const int*)  d_in[21];
    const float* rel_emb = (const float*)d_in[22];
    const float* W_in    = (const float*)d_in[23];
    const float* b_in    = (const float*)d_in[24];
    const float* W_out   = (const float*)d_in[25];
    const float* b_out   = (const float*)d_in[26];
    const float* W_ent   = (const float*)d_in[27];
    const float* b_ent   = (const float*)d_in[28];
    const float* W_rel   = (const float*)d_in[29];
    const float* b_rel   = (const float*)d_in[30];

    const int nB    = in_sizes[21];        // 65536
    const int nrels = in_sizes[22] / 32;   // 1315

    long n4 = (long)6 * nB * 32 / 4;
    zero_kernel<<<4096, 256>>>(n4);
    setup_kernel<<<4, 256>>>(W_in, b_in, W_out, b_out, W_ent, b_ent);
    relprep_kernel<<<(nrels * 32 + 255) / 256, 256>>>(rel_emb, W_rel, b_rel, nrels);

    // 6 incidence matrices: h_in(0), h_out(3), pos_in(7), pos_out(10), neg_in(14), neg_out(17)
    int maxnnz = 0;
    for (int m = 0; m < 6; ++m) {
        const int base = (m >> 1) * 7 + (m & 1) * 3;
        if (in_sizes[base] > maxnnz) maxnnz = in_sizes[base];
    }
    const int nbpm = (maxnnz + 255) / 256;
    scatter6_kernel<<<6 * nbpm, 256>>>(
        (const int*)d_in[0],  (const int*)d_in[1],  (const float*)d_in[2],
        (const int*)d_in[3],  (const int*)d_in[4],  (const float*)d_in[5],
        (const int*)d_in[7],  (const int*)d_in[8],  (const float*)d_in[9],
        (const int*)d_in[10], (const int*)d_in[11], (const float*)d_in[12],
        (const int*)d_in[14], (const int*)d_in[15], (const float*)d_in[16],
        (const int*)d_in[17], (const int*)d_in[18], (const float*)d_in[19],
        in_sizes[0], in_sizes[3], in_sizes[7], in_sizes[10], in_sizes[14], in_sizes[17],
        rel_emb, nB, nbpm);

    ent_emb_kernel<<<3 * (nB / RPB), 256>>>((const float*)d_in[6],
                                            (const float*)d_in[13],
                                            (const float*)d_in[20],
                                            W_ent, nB);

    score_kernel<<<(nB * 8 + 255) / 256, 256>>>(eid, (float*)d_out, nB);
}

// round 17
// speedup vs baseline: 1.3865x; 1.3865x over previous
#include <cuda_runtime.h>

typedef unsigned long long u64;

#define FEAT 768
#define KT   32      // k-tile
#define RPW  16      // rows per warp
#define RPB  128     // rows per block (8 warps)

// ---------------- scratch (device globals; no allocation) ----------------
__device__ float g_agg[6ull * 65536 * 32];   // 6 aggregation buffers [B,32]
__device__ float g_emb[3ull * 65536 * 32];   // h / pos / neg entity embeddings
__device__ float g_R[1344 * 32];             // normalized relation embeddings
__device__ float g_Cin[1024];                // W_ent[:,768:800] @ W_in
__device__ float g_Cout[1024];               // W_ent[:,800:832] @ W_out
__device__ float g_bias[32];                 // folded bias

// ---------------- f32x2 packed-math helpers ----------------
__device__ __forceinline__ u64 ffma2(u64 a, u64 b, u64 c) {
    u64 d;
    asm("fma.rn.f32x2 %0, %1, %2, %3;" : "=l"(d) : "l"(a), "l"(b), "l"(c));
    return d;
}
__device__ __forceinline__ u64 pk(float lo, float hi) {
    u64 r; asm("mov.b64 %0, {%1, %2};" : "=l"(r) : "f"(lo), "f"(hi)); return r;
}
__device__ __forceinline__ float2 upk(u64 v) {
    float2 r; asm("mov.b64 {%0, %1}, %2;" : "=f"(r.x), "=f"(r.y) : "l"(v)); return r;
}

// ---------------- zero the aggregation scratch ----------------
__global__ void zero_kernel(long n4) {
    float4* p = reinterpret_cast<float4*>(g_agg);
    long i = blockIdx.x * (long)blockDim.x + threadIdx.x;
    long stride = (long)gridDim.x * blockDim.x;
    float4 z = make_float4(0.f, 0.f, 0.f, 0.f);
    for (; i < n4; i += stride) p[i] = z;
}

// ---------------- fold W_in/W_out into W_ent tail: C_in/C_out + bias ----------------
__global__ __launch_bounds__(256) void setup_kernel(
        const float* __restrict__ W_in,  const float* __restrict__ b_in,
        const float* __restrict__ W_out, const float* __restrict__ b_out,
        const float* __restrict__ W_ent, const float* __restrict__ b_ent) {
    int gid = blockIdx.x * 256 + threadIdx.x;   // 0..1023
    int j = gid >> 5, d = gid & 31;
    float ci = 0.f, co = 0.f;
    #pragma unroll
    for (int c = 0; c < 32; ++c) {
        ci += W_ent[j * 832 + 768 + c] * W_in[c * 32 + d];
        co += W_ent[j * 832 + 800 + c] * W_out[c * 32 + d];
    }
    g_Cin[j * 32 + d] = ci;
    g_Cout[j * 32 + d] = co;
    if (d == 0) {
        float b = b_ent[j];
        #pragma unroll
        for (int c = 0; c < 32; ++c)
            b += b_in[c] * W_ent[j * 832 + 768 + c] + b_out[c] * W_ent[j * 832 + 800 + c];
        g_bias[j] = b;
    }
}

// ---------------- precompute normalized relation embeddings (1315 rows) ----------------
__global__ void relprep_kernel(const float* __restrict__ rel_emb, const float* __restrict__ W_rel,
                               const float* __restrict__ b_rel, int nrels) {
    int w = (blockIdx.x * blockDim.x + threadIdx.x) >> 5;
    int j = threadIdx.x & 31;
    if (w >= nrels) return;
    float rv = rel_emb[w * 32 + j];
    float acc = b_rel[j];
    const float* wr = W_rel + j * 32;
    #pragma unroll
    for (int d = 0; d < 32; ++d)
        acc = fmaf(__shfl_sync(0xffffffffu, rv, d), __ldg(wr + d), acc);
    float s = acc * acc;
    #pragma unroll
    for (int o = 16; o; o >>= 1) s += __shfl_xor_sync(0xffffffffu, s, o);
    g_R[w * 32 + j] = acc / fmaxf(sqrtf(s), 1e-12f);
}

// ---------------- fused scatter-add over all 6 incidence matrices ----------------
// 8 lanes per nnz: lane q owns float4 #q of the 32-float row. One warp covers
// 4 nnz; each red.v4 instruction touches 4 cache lines (vs 32 in the
// thread-per-nnz layout) -> 8x fewer L1 wavefronts.
__global__ void scatter6_kernel(const int* __restrict__ r0, const int* __restrict__ c0, const float* __restrict__ v0,
                                const int* __restrict__ r1, const int* __restrict__ c1, const float* __restrict__ v1,
                                const int* __restrict__ r2, const int* __restrict__ c2, const float* __restrict__ v2,
                                const int* __restrict__ r3, const int* __restrict__ c3, const float* __restrict__ v3,
                                const int* __restrict__ r4, const int* __restrict__ c4, const float* __restrict__ v4,
                                const int* __restrict__ r5, const int* __restrict__ c5, const float* __restrict__ v5,
                                int n0, int n1, int n2, int n3, int n4_, int n5,
                                const float* __restrict__ rel_emb, int nB, int nbpm) {
    const int m = blockIdx.x / nbpm;
    const long t = (long)(blockIdx.x - m * nbpm) * blockDim.x + threadIdx.x;
    const long e = t >> 3;            // nnz index
    const int  q = (int)t & 7;        // float4 quarter within the 32-float row
    const int* rows; const int* cols; const float* vals; int nnz;
    switch (m) {
        case 0: rows = r0; cols = c0; vals = v0; nnz = n0;  break;
        case 1: rows = r1; cols = c1; vals = v1; nnz = n1;  break;
        case 2: rows = r2; cols = c2; vals = v2; nnz = n2;  break;
        case 3: rows = r3; cols = c3; vals = v3; nnz = n3;  break;
        case 4: rows = r4; cols = c4; vals = v4; nnz = n4_; break;
        default:rows = r5; cols = c5; vals = v5; nnz = n5;  break;
    }
    if (e >= nnz) return;
    const int   r = rows[e];
    const int   c = cols[e];
    const float v = vals[e];
    float4 w = __ldg(reinterpret_cast<const float4*>(rel_emb + (long)c * 32) + q);
    float* dst = g_agg + (long)m * nB * 32 + (long)r * 32 + q * 4;
    asm volatile("red.global.add.v4.f32 [%0], {%1, %2, %3, %4};"
                 :: "l"(dst), "f"(v * w.x), "f"(v * w.y), "f"(v * w.z), "f"(v * w.w)
                 : "memory");
}

// ---------------- entity embedding for ALL 3 sides in one launch ----------------
// e = normalize([feat|agg_in|agg_out] @ M^T + bias); side = blockIdx.x / (nB/RPB)
// Software-pipelined: tile t+1's global loads issue right after tile t's
// staging sync, so LDG latency hides behind tile t's compute.
__global__ __launch_bounds__(256, 2) void ent_emb_kernel(const float* __restrict__ feat_h,
                                                         const float* __restrict__ feat_p,
                                                         const float* __restrict__ feat_n,
                                                         const float* __restrict__ W_ent,
                                                         int nB) {
    __shared__ __align__(16) float As[RPB][KT];   // 16 KB A tile
    __shared__ u64 Ws[KT / 2][32];                // 4 KB W tile, k-paired

    const int tid = threadIdx.x;
    const int warp = tid >> 5, lane = tid & 31;
    const int bpg = nB / RPB;                     // blocks per side
    const int side = blockIdx.x / bpg;
    const int row0 = (blockIdx.x - side * bpg) * RPB;

    const float* feat = (side == 0) ? feat_h : (side == 1) ? feat_p : feat_n;
    const float* aggin  = g_agg + (long)(2 * side)     * nB * 32;
    const float* aggout = g_agg + (long)(2 * side + 1) * nB * 32;
    float*       emb    = g_emb + (long)side * nB * 32;

    u64 acc[RPW];
    #pragma unroll
    for (int i = 0; i < RPW; ++i) acc[i] = 0ull;

    const int sr = tid >> 3;           // staging row (0..31)
    const int sc = (tid & 7) * 4;      // staging col (0,4,..,28)

    float4 a_pre[4];
    float4 w_pre;

    auto load_tile = [&](int t) {
        const float* asrc; long astr;
        if (t < 24)       { asrc = feat   + (long)row0 * FEAT + t * KT; astr = FEAT; }
        else if (t == 24) { asrc = aggin  + (long)row0 * 32;            astr = 32;   }
        else              { asrc = aggout + (long)row0 * 32;            astr = 32;   }
        #pragma unroll
        for (int rr = 0; rr < 4; ++rr)
            a_pre[rr] = *reinterpret_cast<const float4*>(asrc + (long)(sr + rr * 32) * astr + sc);
        const float* wsrc;
        if (t < 24)       wsrc = W_ent + (long)sr * 832 + t * KT + sc;
        else if (t == 24) wsrc = g_Cin  + sr * 32 + sc;
        else              wsrc = g_Cout + sr * 32 + sc;
        w_pre = *reinterpret_cast<const float4*>(wsrc);
    };

    load_tile(0);   // prologue

    for (int t = 0; t < 26; ++t) {
        __syncthreads();   // previous tile's compute done; smem reusable
        // ---- store prefetched tile to smem ----
        #pragma unroll
        for (int rr = 0; rr < 4; ++rr)
            *reinterpret_cast<float4*>(&As[sr + rr * 32][sc]) = a_pre[rr];
        Ws[(sc >> 1)][sr]     = pk(w_pre.x, w_pre.y);
        Ws[(sc >> 1) + 1][sr] = pk(w_pre.z, w_pre.w);
        __syncthreads();
        // ---- issue next tile's global loads (overlap with compute below) ----
        if (t < 25) load_tile(t + 1);
        // ---- W into registers (lane = output col), reused over RPW rows ----
        u64 wreg[KT / 2];
        #pragma unroll
        for (int p = 0; p < KT / 2; ++p) wreg[p] = Ws[p][lane];
        // ---- packed FMA mainloop: chunk-outer / row-inner for ILP ----
        #pragma unroll
        for (int c = 0; c < KT / 4; ++c) {
            #pragma unroll
            for (int rr = 0; rr < RPW; ++rr) {
                const int r = warp * RPW + rr;
                ulonglong2 a = *reinterpret_cast<const ulonglong2*>(&As[r][c * 4]);
                acc[rr] = ffma2(a.x, wreg[2 * c],     acc[rr]);
                acc[rr] = ffma2(a.y, wreg[2 * c + 1], acc[rr]);
            }
        }
    }
    // ---- epilogue: bias, row-norm, write ----
    float bj = g_bias[lane];
    #pragma unroll
    for (int rr = 0; rr < RPW; ++rr) {
        float2 p = upk(acc[rr]);
        float e = p.x + p.y + bj;
        float s = e * e;
        #pragma unroll
        for (int o = 16; o; o >>= 1) s += __shfl_xor_sync(0xffffffffu, s, o);
        float inv = 1.f / fmaxf(sqrtf(s), 1e-12f);
        emb[(long)(row0 + warp * RPW + rr) * 32 + lane] = e * inv;
    }
}

// ---------------- scores: 8 lanes per entity, float4 per lane ----------------
__global__ void score_kernel(const int* __restrict__ eid, float* __restrict__ out, int nB) {
    int gt = blockIdx.x * blockDim.x + threadIdx.x;
    int ent = gt >> 3;
    if (ent >= nB) return;
    int sub = gt & 7;
    int e = eid[ent];
    const float4* R4 = reinterpret_cast<const float4*>(g_R);
    const float4* h4 = reinterpret_cast<const float4*>(g_emb);
    const float4* p4 = h4 + (long)nB * 8;
    const float4* n4 = h4 + (long)2 * nB * 8;
    float4 r = R4[e * 8 + sub];
    float4 h = h4[(long)ent * 8 + sub];
    float4 p = p4[(long)ent * 8 + sub];
    float4 n = n4[(long)ent * 8 + sub];
    float hx = h.x + r.x, hy = h.y + r.y, hz = h.z + r.z, hw = h.w + r.w;
    float dx, dy, dz, dw;
    dx = hx - p.x; dy = hy - p.y; dz = hz - p.z; dw = hw - p.w;
    float sp = dx * dx + dy * dy + dz * dz + dw * dw;
    dx = hx - n.x; dy = hy - n.y; dz = hz - n.z; dw = hw - n.w;
    float sn = dx * dx + dy * dy + dz * dz + dw * dw;
    #pragma unroll
    for (int o = 4; o; o >>= 1) {
        sp += __shfl_xor_sync(0xffffffffu, sp, o);
        sn += __shfl_xor_sync(0xffffffffu, sn, o);
    }
    if (sub == 0) {
        out[ent]      = sqrtf(sp);
        out[nB + ent] = sqrtf(sn);
    }
}

// ---------------- launch ----------------
extern "C" void kernel_launch(void* const* d_in, const int* in_sizes, int n_in,
                              void* d_out, int out_size) {
    const int*   eid     = (const int*)  d_in[21];
    const float* rel_emb = (const float*)d_in[22];
    const float* W_in    = (const float*)d_in[23];
    const float* b_in    = (const float*)d_in[24];
    const float* W_out   = (const float*)d_in[25];
    const float* b_out   = (const float*)d_in[26];
    const float* W_ent   = (const float*)d_in[27];
    const float* b_ent   = (const float*)d_in[28];
    const float* W_rel   = (const float*)d_in[29];
    const float* b_rel   = (const float*)d_in[30];

    const int nB    = in_sizes[21];        // 65536
    const int nrels = in_sizes[22] / 32;   // 1315

    long n4 = (long)6 * nB * 32 / 4;
    zero_kernel<<<4096, 256>>>(n4);
    setup_kernel<<<4, 256>>>(W_in, b_in, W_out, b_out, W_ent, b_ent);
    relprep_kernel<<<(nrels * 32 + 255) / 256, 256>>>(rel_emb, W_rel, b_rel, nrels);

    // 6 incidence matrices: h_in(0), h_out(3), pos_in(7), pos_out(10), neg_in(14), neg_out(17)
    int maxnnz = 0;
    for (int m = 0; m < 6; ++m) {
        const int base = (m >> 1) * 7 + (m & 1) * 3;
        if (in_sizes[base] > maxnnz) maxnnz = in_sizes[base];
    }
    // 8 threads per nnz
    const long maxthreads = (long)maxnnz * 8;
    const int nbpm = (int)((maxthreads + 255) / 256);
    scatter6_kernel<<<6 * nbpm, 256>>>(
        (const int*)d_in[0],  (const int*)d_in[1],  (const float*)d_in[2],
        (const int*)d_in[3],  (const int*)d_in[4],  (const float*)d_in[5],
        (const int*)d_in[7],  (const int*)d_in[8],  (const float*)d_in[9],
        (const int*)d_in[10], (const int*)d_in[11], (const float*)d_in[12],
        (const int*)d_in[14], (const int*)d_in[15], (const float*)d_in[16],
        (const int*)d_in[17], (const int*)d_in[18], (const float*)d_in[19],
        in_sizes[0], in_sizes[3], in_sizes[7], in_sizes[10], in_sizes[14], in_sizes[17],
        rel_emb, nB, nbpm);

    ent_emb_kernel<<<3 * (nB / RPB), 256>>>((const float*)d_in[6],
                                            (const float*)d_in[13],
                                            (const float*)d_in[20],
                                            W_ent, nB);

    score_kernel<<<(nB * 8 + 255) / 256, 256>>>(eid, (float*)d_out, nB);
}